// round 13
// baseline (speedup 1.0000x reference)
#include <cuda_runtime.h>
#include <cuda_fp16.h>
#include <math.h>
#include <cstdint>

#define Bn 2
#define Sn 2048
#define Dn 1024
#define Hn 16
#define HDn 64
#define NEGV -1.0e9f

// Scratch (device globals: no allocations allowed)
__device__ __half g_xh[Bn*Sn*Dn];        // X in half
__device__ __half g_wh[4*Dn*Dn];         // Wq,Wk,Wv,Wo in half
__device__ __half g_qh[Bn*Hn*Sn*HDn];    // [B,H,S,HD] (pre-scaled by 0.125)
__device__ __half g_kh[Bn*Hn*Sn*HDn];
__device__ __half g_vh[Bn*Hn*Sn*HDn];
__device__ __half g_ctx[Bn*Sn*Dn];       // [B,S,D] context before Wo

__device__ __forceinline__ void mma_f16(float* c, const uint32_t* a,
                                        uint32_t b0, uint32_t b1) {
    asm volatile(
        "mma.sync.aligned.m16n8k16.row.col.f32.f16.f16.f32 "
        "{%0,%1,%2,%3}, {%4,%5,%6,%7}, {%8,%9}, {%0,%1,%2,%3};"
        : "+f"(c[0]), "+f"(c[1]), "+f"(c[2]), "+f"(c[3])
        : "r"(a[0]), "r"(a[1]), "r"(a[2]), "r"(a[3]), "r"(b0), "r"(b1));
}

__device__ __forceinline__ uint32_t pack_h2(float x, float y) {
    __half2 h = __floats2half2_rn(x, y);
    return *reinterpret_cast<uint32_t*>(&h);
}

__device__ __forceinline__ uint32_t smem_u32(const void* p) {
    uint32_t a;
    asm("{ .reg .u64 t; cvta.to.shared.u64 t, %1; cvt.u32.u64 %0, t; }"
        : "=r"(a) : "l"(p));
    return a;
}

#define CP16(dst_u32, src_ptr)                                               \
    asm volatile("cp.async.cg.shared.global [%0], [%1], 16;"                 \
                 :: "r"(dst_u32), "l"(src_ptr))
#define CP_COMMIT() asm volatile("cp.async.commit_group;" ::: "memory")
#define CP_WAIT(N)  asm volatile("cp.async.wait_group %0;" :: "n"(N) : "memory")

#define LDSM4(r0, r1, r2, r3, addr)                                          \
    asm volatile("ldmatrix.sync.aligned.m8n8.x4.shared.b16 {%0,%1,%2,%3}, [%4];" \
                 : "=r"(r0), "=r"(r1), "=r"(r2), "=r"(r3) : "r"(addr))
#define LDSM4T(r0, r1, r2, r3, addr)                                         \
    asm volatile("ldmatrix.sync.aligned.m8n8.x4.trans.shared.b16 {%0,%1,%2,%3}, [%4];" \
                 : "=r"(r0), "=r"(r1), "=r"(r2), "=r"(r3) : "r"(addr))

// ===========================================================================
// Pre-conversion: X + 4 weight matrices -> half.  (unchanged from R12)
// ===========================================================================
__global__ void __launch_bounds__(256) cvt_inputs(const float4* __restrict__ X,
                                                  const float4* __restrict__ Wq,
                                                  const float4* __restrict__ Wk,
                                                  const float4* __restrict__ Wv,
                                                  const float4* __restrict__ Wo)
{
    const int idx = blockIdx.x * 256 + threadIdx.x;
    const int XQ = (Bn * Sn * Dn) / 4;
    float4 v;
    uint2* dst;
    if (idx < XQ) {
        v = X[idx];
        dst = reinterpret_cast<uint2*>(g_xh) + idx;
    } else {
        const int j = idx - XQ;
        const int which = j >> 18;
        const int off = j & ((1 << 18) - 1);
        const float4* W = (which == 0) ? Wq : (which == 1) ? Wk
                        : (which == 2) ? Wv : Wo;
        v = W[off];
        dst = reinterpret_cast<uint2*>(g_wh) + (which << 18) + off;
    }
    uint2 u;
    u.x = pack_h2(v.x, v.y);
    u.y = pack_h2(v.z, v.w);
    *dst = u;
}

// ===========================================================================
// fp16 cp.async GEMM (unchanged from R12 — QKV fused + Wo)
// ===========================================================================
#define BM 128
#define BN 128
#define BKH2 64
#define GSTAGES (Dn / BKH2)
#define TILE_W 4096
#define GEMM_SMEM (4 * TILE_W * 4)

template<int QKV>
__global__ void __launch_bounds__(256, 2)
gemm_cp(const __half* __restrict__ Xh,
        const __half* __restrict__ Wh,
        const float* __restrict__ bias0,
        const float* __restrict__ bias1,
        const float* __restrict__ bias2,
        __half* __restrict__ Y0,
        __half* __restrict__ Y1,
        __half* __restrict__ Y2,
        float* __restrict__ Yf)
{
    extern __shared__ uint32_t smem[];
    const uint32_t smem_b = smem_u32(smem);

    const int t  = threadIdx.x;
    const int w  = t >> 5;
    const int ln = t & 31;
    const int g  = ln >> 2;
    const int q  = ln & 3;
    const int wm = (w & 3) * 32;
    const int wn = (w >> 2) * 64;
    const int rowBase = blockIdx.y * BM;

    int which = 0, colW = blockIdx.x * BN;
    if (QKV) { which = blockIdx.x >> 3; colW = (blockIdx.x & 7) * BN; }
    const __half* W    = Wh + (size_t)which * Dn * Dn;
    const float* bias  = (which == 0) ? bias0 : (which == 1) ? bias1 : bias2;
    __half*      Y     = (which == 0) ? Y0 : (which == 1) ? Y1 : Y2;
    const float  scale = (QKV && which == 0) ? 0.125f : 1.0f;

    float acc[2][8][4];
#pragma unroll
    for (int mt = 0; mt < 2; mt++)
#pragma unroll
        for (int nt = 0; nt < 8; nt++)
#pragma unroll
            for (int r = 0; r < 4; r++) acc[mt][nt][r] = 0.f;

    auto issue = [&](int s) {
        const int buf = s & 1;
        const int k0 = s * BKH2;
        const uint32_t aB = smem_b + (buf * 2 * TILE_W) * 4;
        const uint32_t bB = aB + TILE_W * 4;
#pragma unroll
        for (int i = 0; i < 4; i++) {
            const int e = t + 256 * i;
            const int m = e >> 3, c = e & 7;
            const uint32_t swoff = (uint32_t)(m * 128 + ((c ^ (m & 7)) << 4));
            CP16(aB + swoff, &Xh[(size_t)(rowBase + m) * Dn + k0 + c * 8]);
            CP16(bB + swoff, &W[(size_t)(colW + m) * Dn + k0 + c * 8]);
        }
        CP_COMMIT();
    };

    auto comp = [&](int buf) {
        const uint32_t* A = smem + buf * 2 * TILE_W;
        const uint32_t* B = A + TILE_W;
#pragma unroll
        for (int kk = 0; kk < 4; kk++) {
            const int c0 = 2 * kk, c1 = 2 * kk + 1;
            uint32_t af[2][4];
#pragma unroll
            for (int mt = 0; mt < 2; mt++) {
                const int m = wm + mt * 16 + g;
                af[mt][0] = A[m * 32 + ((c0 ^ g) << 2) + q];
                af[mt][1] = A[(m + 8) * 32 + ((c0 ^ g) << 2) + q];
                af[mt][2] = A[m * 32 + ((c1 ^ g) << 2) + q];
                af[mt][3] = A[(m + 8) * 32 + ((c1 ^ g) << 2) + q];
            }
#pragma unroll
            for (int nt = 0; nt < 8; nt++) {
                const int n = wn + nt * 8 + g;
                const uint32_t b0 = B[n * 32 + ((c0 ^ g) << 2) + q];
                const uint32_t b1 = B[n * 32 + ((c1 ^ g) << 2) + q];
                mma_f16(acc[0][nt], af[0], b0, b1);
                mma_f16(acc[1][nt], af[1], b0, b1);
            }
        }
    };

    issue(0);
    issue(1);
    for (int s = 0; s < GSTAGES; s++) {
        if (s + 1 < GSTAGES) CP_WAIT(1); else CP_WAIT(0);
        __syncthreads();
        comp(s & 1);
        if (s + 2 < GSTAGES) {
            __syncthreads();
            issue(s + 2);
        }
    }

#pragma unroll
    for (int nt = 0; nt < 8; nt++) {
        const int c = colW + wn + nt * 8 + 2 * q;
        const float b0 = bias[c], b1 = bias[c + 1];
#pragma unroll
        for (int mt = 0; mt < 2; mt++) {
            const int r0 = rowBase + wm + mt * 16 + g;
#pragma unroll
            for (int half = 0; half < 2; half++) {
                const int rr = r0 + half * 8;
                const float vx = (acc[mt][nt][half * 2 + 0] + b0) * scale;
                const float vy = (acc[mt][nt][half * 2 + 1] + b1) * scale;
                if (QKV) {
                    const int bb = rr >> 11;
                    const int ss = rr & (Sn - 1);
                    const int hh = c >> 6;
                    const int dd = c & (HDn - 1);
                    *(uint32_t*)&Y[(size_t)((bb * Hn + hh) * Sn + ss) * HDn + dd] =
                        pack_h2(vx, vy);
                } else {
                    float2 v; v.x = vx; v.y = vy;
                    *(float2*)&Yf[(size_t)rr * Dn + c] = v;
                }
            }
        }
    }
}

// ===========================================================================
// Flash attention, fp16 mma + ldmatrix fragment loads. BQ=BK=64, HD=64.
// 128 threads = 4 warps. All tiles natural row-major, stride 72 halves
// (144 B = 9x16B -> (row+chunk)%8 distinct => ldmatrix conflict-free).
// V transposition is done by ldmatrix.trans (no scalar-LDG transpose).
// qt reversed so longest causal CTAs launch first.
// ===========================================================================
#define PSTR 36                              // words per row (72 halves)
#define FA_SMEM ((4 * 64 * PSTR + 64) * 4)   // 37120 B

__global__ void __launch_bounds__(128) flash_attn_h(const __half* __restrict__ qh,
                                                    const __half* __restrict__ kh,
                                                    const __half* __restrict__ vh,
                                                    const int* __restrict__ pad,
                                                    __half* __restrict__ ctx)
{
    extern __shared__ uint32_t sm[];
    uint32_t* Qs = sm;                 // [64][36w] natural
    uint32_t* Ks = Qs + 64 * PSTR;
    uint32_t* Vs = Ks + 64 * PSTR;     // natural [key][d]
    uint32_t* Ps = Vs + 64 * PSTR;
    float*    PM = (float*)(Ps + 64 * PSTR);

    const uint32_t Qu = smem_u32(sm);
    const uint32_t Ku = Qu + 64 * PSTR * 4;
    const uint32_t Vu = Ku + 64 * PSTR * 4;
    const uint32_t Pu = Vu + 64 * PSTR * 4;

    const int t  = threadIdx.x;
    const int w  = t >> 5;
    const int ln = t & 31;
    const int g  = ln >> 2;
    const int q  = ln & 3;
    const int qt = (int)gridDim.x - 1 - (int)blockIdx.x;   // longest first
    const int h  = blockIdx.y;
    const int b  = blockIdx.z;
    const int q0 = qt * 64;
    const int wq = w * 16;

    // ldmatrix lane->address offsets (derivation in round notes)
    const int r8   = ln & 7;
    const int aRow = wq + ((ln >> 3) & 1) * 8 + r8;   // A (Q,P): rows
    const int aCol = ((ln >> 4) & 1) * 8;             // A: col offset
    const int kRow = ((ln >> 4) & 1) * 8 + r8;        // K B-frag row offset
    const int kCol = ((ln >> 3) & 1) * 8;             // K B-frag col offset
    const int vRow = ((ln >> 3) & 1) * 8 + r8;        // V B-frag (trans) row
    const int vCol = ((ln >> 4) & 1) * 8;             // V B-frag col offset

    const uint32_t aQbase = Qu + (uint32_t)(aRow * 144 + aCol * 2);
    const uint32_t aPbase = Pu + (uint32_t)(aRow * 144 + aCol * 2);

    const __half* qb = qh + (size_t)((b * Hn + h) * Sn + q0) * HDn;
    const __half* kb = kh + (size_t)((b * Hn + h) * Sn) * HDn;
    const __half* vb = vh + (size_t)((b * Hn + h) * Sn) * HDn;

    // Q tile: vectorized copy (already scaled + half)
#pragma unroll
    for (int i = 0; i < 4; i++) {
        const int cc  = t + 128 * i;
        const int row = cc >> 3;
        const int c8  = cc & 7;
        uint4 u = *(const uint4*)&qb[row * HDn + c8 * 8];
        *(uint4*)&Qs[row * PSTR + c8 * 4] = u;
    }

    float o[8][4];
#pragma unroll
    for (int dt = 0; dt < 8; dt++)
#pragma unroll
        for (int r = 0; r < 4; r++) o[dt][r] = 0.f;
    float mrow[2] = {-1e30f, -1e30f};
    float lrow[2] = {0.f, 0.f};

    const int r_lo = q0 + wq + g;
    const int r_hi = r_lo + 8;

    for (int kt = 0; kt <= qt; kt++) {
        const int k0 = kt * 64;
        __syncthreads();

        // K and V tiles: vectorized natural copies
#pragma unroll
        for (int i = 0; i < 4; i++) {
            const int cc  = t + 128 * i;
            const int row = cc >> 3;
            const int c8  = cc & 7;
            uint4 uk = *(const uint4*)&kb[(size_t)(k0 + row) * HDn + c8 * 8];
            *(uint4*)&Ks[row * PSTR + c8 * 4] = uk;
            uint4 uv = *(const uint4*)&vb[(size_t)(k0 + row) * HDn + c8 * 8];
            *(uint4*)&Vs[row * PSTR + c8 * 4] = uv;
        }
        if (t < 64) PM[t] = (pad[b * Sn + k0 + t] != 0) ? 1.f : 0.f;
        __syncthreads();

        // ---- S = Q K^T ----
        float sv[8][4];
#pragma unroll
        for (int nt = 0; nt < 8; nt++)
#pragma unroll
            for (int r = 0; r < 4; r++) sv[nt][r] = 0.f;

#pragma unroll
        for (int kk = 0; kk < 4; kk++) {
            uint32_t a[4];
            LDSM4(a[0], a[1], a[2], a[3], aQbase + kk * 32);
#pragma unroll
            for (int p = 0; p < 4; p++) {
                uint32_t b0a, b1a, b0b, b1b;
                LDSM4(b0a, b1a, b0b, b1b,
                      Ku + (uint32_t)((16 * p + kRow) * 144 + (16 * kk + kCol) * 2));
                mma_f16(sv[2 * p],     a, b0a, b1a);
                mma_f16(sv[2 * p + 1], a, b0b, b1b);
            }
        }

        // ---- mask (replace semantics) ----
        const bool diag = (kt == qt);
#pragma unroll
        for (int nt = 0; nt < 8; nt++) {
            const int kx0 = nt * 8 + 2 * q;
            const bool pm0 = PM[kx0] != 0.f;
            const bool pm1 = PM[kx0 + 1] != 0.f;
            const int kg0 = k0 + kx0, kg1 = kg0 + 1;
            if (pm0 || (diag && kg0 > r_lo)) sv[nt][0] = NEGV;
            if (pm1 || (diag && kg1 > r_lo)) sv[nt][1] = NEGV;
            if (pm0 || (diag && kg0 > r_hi)) sv[nt][2] = NEGV;
            if (pm1 || (diag && kg1 > r_hi)) sv[nt][3] = NEGV;
        }

        // ---- online softmax ----
#pragma unroll
        for (int half = 0; half < 2; half++) {
            const int ci = half * 2;
            float tm = -1e30f;
#pragma unroll
            for (int nt = 0; nt < 8; nt++)
                tm = fmaxf(tm, fmaxf(sv[nt][ci], sv[nt][ci + 1]));
            tm = fmaxf(tm, __shfl_xor_sync(0xffffffffu, tm, 1));
            tm = fmaxf(tm, __shfl_xor_sync(0xffffffffu, tm, 2));
            const float mnew = fmaxf(mrow[half], tm);
            const float sc = __expf(mrow[half] - mnew);
            float rs = 0.f;
#pragma unroll
            for (int nt = 0; nt < 8; nt++) {
                const float p0 = __expf(sv[nt][ci]     - mnew);
                const float p1 = __expf(sv[nt][ci + 1] - mnew);
                sv[nt][ci] = p0; sv[nt][ci + 1] = p1;
                rs += p0 + p1;
            }
            rs += __shfl_xor_sync(0xffffffffu, rs, 1);
            rs += __shfl_xor_sync(0xffffffffu, rs, 2);
            lrow[half] = lrow[half] * sc + rs;
            mrow[half] = mnew;
#pragma unroll
            for (int dt = 0; dt < 8; dt++) {
                o[dt][ci]     *= sc;
                o[dt][ci + 1] *= sc;
            }
        }

        // ---- store P (natural row-major pairs) ----
#pragma unroll
        for (int nt = 0; nt < 8; nt++) {
            Ps[(wq + g)     * PSTR + 4 * nt + q] = pack_h2(sv[nt][0], sv[nt][1]);
            Ps[(wq + g + 8) * PSTR + 4 * nt + q] = pack_h2(sv[nt][2], sv[nt][3]);
        }
        __syncwarp();

        // ---- O += P V  (V transposed by ldmatrix.trans) ----
#pragma unroll
        for (int kk = 0; kk < 4; kk++) {
            uint32_t a[4];
            LDSM4(a[0], a[1], a[2], a[3], aPbase + kk * 32);
#pragma unroll
            for (int p = 0; p < 4; p++) {
                uint32_t b0a, b1a, b0b, b1b;
                LDSM4T(b0a, b1a, b0b, b1b,
                       Vu + (uint32_t)((16 * kk + vRow) * 144 + (16 * p + vCol) * 2));
                mma_f16(o[2 * p],     a, b0a, b1a);
                mma_f16(o[2 * p + 1], a, b0b, b1b);
            }
        }
    }

    // ---- normalize + write half context ----
    const float inv_lo = 1.f / lrow[0];
    const float inv_hi = 1.f / lrow[1];
#pragma unroll
    for (int dt = 0; dt < 8; dt++) {
        const int col = h * HDn + dt * 8 + 2 * q;
        *(uint32_t*)&ctx[(size_t)(b * Sn + r_lo) * Dn + col] =
            pack_h2(o[dt][0] * inv_lo, o[dt][1] * inv_lo);
        *(uint32_t*)&ctx[(size_t)(b * Sn + r_hi) * Dn + col] =
            pack_h2(o[dt][2] * inv_hi, o[dt][3] * inv_hi);
    }
}

// ---------------------------------------------------------------------------
extern "C" void kernel_launch(void* const* d_in, const int* in_sizes, int n_in,
                              void* d_out, int out_size)
{
    const float* x    = (const float*)d_in[0];
    const int*   pm   = (const int*)d_in[1];
    const float* Wq   = (const float*)d_in[2];
    const float* bq   = (const float*)d_in[3];
    const float* Wk   = (const float*)d_in[4];
    const float* bk   = (const float*)d_in[5];
    const float* Wv   = (const float*)d_in[6];
    const float* bv   = (const float*)d_in[7];
    const float* Wo   = (const float*)d_in[8];
    const float* bo   = (const float*)d_in[9];
    float* out = (float*)d_out;

    __half *xh, *wh, *qh, *kh, *vh, *ctx;
    cudaGetSymbolAddress((void**)&xh,  g_xh);
    cudaGetSymbolAddress((void**)&wh,  g_wh);
    cudaGetSymbolAddress((void**)&qh,  g_qh);
    cudaGetSymbolAddress((void**)&kh,  g_kh);
    cudaGetSymbolAddress((void**)&vh,  g_vh);
    cudaGetSymbolAddress((void**)&ctx, g_ctx);

    cudaFuncSetAttribute(gemm_cp<1>, cudaFuncAttributeMaxDynamicSharedMemorySize,
                         GEMM_SMEM);
    cudaFuncSetAttribute(gemm_cp<0>, cudaFuncAttributeMaxDynamicSharedMemorySize,
                         GEMM_SMEM);
    cudaFuncSetAttribute(flash_attn_h, cudaFuncAttributeMaxDynamicSharedMemorySize,
                         FA_SMEM);

    cvt_inputs<<<8192, 256>>>((const float4*)x, (const float4*)Wq,
                              (const float4*)Wk, (const float4*)Wv,
                              (const float4*)Wo);

    const dim3 qkv_grid(24, (Bn * Sn) / BM);     // (24, 32)
    gemm_cp<1><<<qkv_grid, 256, GEMM_SMEM>>>(xh, wh, bq, bk, bv,
                                             qh, kh, vh, nullptr);

    dim3 agrid(Sn / 64, Hn, Bn);  // (32, 16, 2)
    flash_attn_h<<<agrid, 128, FA_SMEM>>>(qh, kh, vh, pm, ctx);

    const dim3 o_grid(Dn / BN, (Bn * Sn) / BM);  // (8, 32)
    gemm_cp<0><<<o_grid, 256, GEMM_SMEM>>>(ctx, wh + (size_t)3 * Dn * Dn,
                                           bo, nullptr, nullptr,
                                           nullptr, nullptr, nullptr, out);
}

// round 14
// speedup vs baseline: 1.5027x; 1.5027x over previous
#include <cuda_runtime.h>
#include <cuda_fp16.h>
#include <math.h>
#include <cstdint>

#define Bn 2
#define Sn 2048
#define Dn 1024
#define Hn 16
#define HDn 64
#define NEGV -1.0e9f

// Scratch (device globals: no allocations allowed)
__device__ __half g_xh[Bn*Sn*Dn];        // X in half
__device__ __half g_wh[4*Dn*Dn];         // Wq,Wk,Wv,Wo in half
__device__ __half g_qh[Bn*Hn*Sn*HDn];    // [B,H,S,HD] (pre-scaled by 0.125)
__device__ __half g_kh[Bn*Hn*Sn*HDn];
__device__ __half g_vh[Bn*Hn*Sn*HDn];
__device__ __half g_ctx[Bn*Sn*Dn];       // [B,S,D] context before Wo

__device__ __forceinline__ void mma_f16(float* c, const uint32_t* a,
                                        uint32_t b0, uint32_t b1) {
    asm volatile(
        "mma.sync.aligned.m16n8k16.row.col.f32.f16.f16.f32 "
        "{%0,%1,%2,%3}, {%4,%5,%6,%7}, {%8,%9}, {%0,%1,%2,%3};"
        : "+f"(c[0]), "+f"(c[1]), "+f"(c[2]), "+f"(c[3])
        : "r"(a[0]), "r"(a[1]), "r"(a[2]), "r"(a[3]), "r"(b0), "r"(b1));
}

__device__ __forceinline__ uint32_t pack_h2(float x, float y) {
    __half2 h = __floats2half2_rn(x, y);
    return *reinterpret_cast<uint32_t*>(&h);
}

__device__ __forceinline__ uint32_t smem_u32(const void* p) {
    uint32_t a;
    asm("{ .reg .u64 t; cvta.to.shared.u64 t, %1; cvt.u32.u64 %0, t; }"
        : "=r"(a) : "l"(p));
    return a;
}

#define CP16(dst_u32, src_ptr)                                               \
    asm volatile("cp.async.cg.shared.global [%0], [%1], 16;"                 \
                 :: "r"(dst_u32), "l"(src_ptr))
#define CP_COMMIT() asm volatile("cp.async.commit_group;" ::: "memory")
#define CP_WAIT(N)  asm volatile("cp.async.wait_group %0;" :: "n"(N) : "memory")

#define LDSM4(r0, r1, r2, r3, addr)                                          \
    asm volatile("ldmatrix.sync.aligned.m8n8.x4.shared.b16 {%0,%1,%2,%3}, [%4];" \
                 : "=r"(r0), "=r"(r1), "=r"(r2), "=r"(r3) : "r"(addr))
#define LDSM4T(r0, r1, r2, r3, addr)                                         \
    asm volatile("ldmatrix.sync.aligned.m8n8.x4.trans.shared.b16 {%0,%1,%2,%3}, [%4];" \
                 : "=r"(r0), "=r"(r1), "=r"(r2), "=r"(r3) : "r"(addr))

// ===========================================================================
// Pre-conversion: X + 4 weight matrices -> half.  (unchanged)
// ===========================================================================
__global__ void __launch_bounds__(256) cvt_inputs(const float4* __restrict__ X,
                                                  const float4* __restrict__ Wq,
                                                  const float4* __restrict__ Wk,
                                                  const float4* __restrict__ Wv,
                                                  const float4* __restrict__ Wo)
{
    const int idx = blockIdx.x * 256 + threadIdx.x;
    const int XQ = (Bn * Sn * Dn) / 4;
    float4 v;
    uint2* dst;
    if (idx < XQ) {
        v = X[idx];
        dst = reinterpret_cast<uint2*>(g_xh) + idx;
    } else {
        const int j = idx - XQ;
        const int which = j >> 18;
        const int off = j & ((1 << 18) - 1);
        const float4* W = (which == 0) ? Wq : (which == 1) ? Wk
                        : (which == 2) ? Wv : Wo;
        v = W[off];
        dst = reinterpret_cast<uint2*>(g_wh) + (which << 18) + off;
    }
    uint2 u;
    u.x = pack_h2(v.x, v.y);
    u.y = pack_h2(v.z, v.w);
    *dst = u;
}

// ===========================================================================
// fp16 cp.async GEMM (unchanged — QKV fused + Wo)
// ===========================================================================
#define BM 128
#define BN 128
#define BKH2 64
#define GSTAGES (Dn / BKH2)
#define TILE_W 4096
#define GEMM_SMEM (4 * TILE_W * 4)

template<int QKV>
__global__ void __launch_bounds__(256, 2)
gemm_cp(const __half* __restrict__ Xh,
        const __half* __restrict__ Wh,
        const float* __restrict__ bias0,
        const float* __restrict__ bias1,
        const float* __restrict__ bias2,
        __half* __restrict__ Y0,
        __half* __restrict__ Y1,
        __half* __restrict__ Y2,
        float* __restrict__ Yf)
{
    extern __shared__ uint32_t smem[];
    const uint32_t smem_b = smem_u32(smem);

    const int t  = threadIdx.x;
    const int w  = t >> 5;
    const int ln = t & 31;
    const int g  = ln >> 2;
    const int q  = ln & 3;
    const int wm = (w & 3) * 32;
    const int wn = (w >> 2) * 64;
    const int rowBase = blockIdx.y * BM;

    int which = 0, colW = blockIdx.x * BN;
    if (QKV) { which = blockIdx.x >> 3; colW = (blockIdx.x & 7) * BN; }
    const __half* W    = Wh + (size_t)which * Dn * Dn;
    const float* bias  = (which == 0) ? bias0 : (which == 1) ? bias1 : bias2;
    __half*      Y     = (which == 0) ? Y0 : (which == 1) ? Y1 : Y2;
    const float  scale = (QKV && which == 0) ? 0.125f : 1.0f;

    float acc[2][8][4];
#pragma unroll
    for (int mt = 0; mt < 2; mt++)
#pragma unroll
        for (int nt = 0; nt < 8; nt++)
#pragma unroll
            for (int r = 0; r < 4; r++) acc[mt][nt][r] = 0.f;

    auto issue = [&](int s) {
        const int buf = s & 1;
        const int k0 = s * BKH2;
        const uint32_t aB = smem_b + (buf * 2 * TILE_W) * 4;
        const uint32_t bB = aB + TILE_W * 4;
#pragma unroll
        for (int i = 0; i < 4; i++) {
            const int e = t + 256 * i;
            const int m = e >> 3, c = e & 7;
            const uint32_t swoff = (uint32_t)(m * 128 + ((c ^ (m & 7)) << 4));
            CP16(aB + swoff, &Xh[(size_t)(rowBase + m) * Dn + k0 + c * 8]);
            CP16(bB + swoff, &W[(size_t)(colW + m) * Dn + k0 + c * 8]);
        }
        CP_COMMIT();
    };

    auto comp = [&](int buf) {
        const uint32_t* A = smem + buf * 2 * TILE_W;
        const uint32_t* B = A + TILE_W;
#pragma unroll
        for (int kk = 0; kk < 4; kk++) {
            const int c0 = 2 * kk, c1 = 2 * kk + 1;
            uint32_t af[2][4];
#pragma unroll
            for (int mt = 0; mt < 2; mt++) {
                const int m = wm + mt * 16 + g;
                af[mt][0] = A[m * 32 + ((c0 ^ g) << 2) + q];
                af[mt][1] = A[(m + 8) * 32 + ((c0 ^ g) << 2) + q];
                af[mt][2] = A[m * 32 + ((c1 ^ g) << 2) + q];
                af[mt][3] = A[(m + 8) * 32 + ((c1 ^ g) << 2) + q];
            }
#pragma unroll
            for (int nt = 0; nt < 8; nt++) {
                const int n = wn + nt * 8 + g;
                const uint32_t b0 = B[n * 32 + ((c0 ^ g) << 2) + q];
                const uint32_t b1 = B[n * 32 + ((c1 ^ g) << 2) + q];
                mma_f16(acc[0][nt], af[0], b0, b1);
                mma_f16(acc[1][nt], af[1], b0, b1);
            }
        }
    };

    issue(0);
    issue(1);
    for (int s = 0; s < GSTAGES; s++) {
        if (s + 1 < GSTAGES) CP_WAIT(1); else CP_WAIT(0);
        __syncthreads();
        comp(s & 1);
        if (s + 2 < GSTAGES) {
            __syncthreads();
            issue(s + 2);
        }
    }

#pragma unroll
    for (int nt = 0; nt < 8; nt++) {
        const int c = colW + wn + nt * 8 + 2 * q;
        const float b0 = bias[c], b1 = bias[c + 1];
#pragma unroll
        for (int mt = 0; mt < 2; mt++) {
            const int r0 = rowBase + wm + mt * 16 + g;
#pragma unroll
            for (int half = 0; half < 2; half++) {
                const int rr = r0 + half * 8;
                const float vx = (acc[mt][nt][half * 2 + 0] + b0) * scale;
                const float vy = (acc[mt][nt][half * 2 + 1] + b1) * scale;
                if (QKV) {
                    const int bb = rr >> 11;
                    const int ss = rr & (Sn - 1);
                    const int hh = c >> 6;
                    const int dd = c & (HDn - 1);
                    *(uint32_t*)&Y[(size_t)((bb * Hn + hh) * Sn + ss) * HDn + dd] =
                        pack_h2(vx, vy);
                } else {
                    float2 v; v.x = vx; v.y = vy;
                    *(float2*)&Yf[(size_t)rr * Dn + c] = v;
                }
            }
        }
    }
}

// ===========================================================================
// Flash attention: fp16 mma + ldmatrix fragments + cp.async K/V double-buffer.
// BQ=BK=64, HD=64, 128 threads = 4 warps. Natural row-major tiles, stride 72
// halves (144 B). Layout (words): Q=0, K0=2304, K1=4608, V0=6912, V1=9216,
// P=11520, PM=13824. Total 55552 B -> 4 CTAs/SM by smem.
// ===========================================================================
#define PSTR 36
#define FAW_K 2304
#define FAW_V 6912
#define FAW_P 11520
#define FAW_PM 13824
#define FA_SMEM ((13824 + 64) * 4)           // 55552 B

__global__ void __launch_bounds__(128) flash_attn_h(const __half* __restrict__ qh,
                                                    const __half* __restrict__ kh,
                                                    const __half* __restrict__ vh,
                                                    const int* __restrict__ pad,
                                                    __half* __restrict__ ctx)
{
    extern __shared__ uint32_t sm[];
    uint32_t* Qs = sm;
    uint32_t* Ps = sm + FAW_P;
    float*    PM = (float*)(sm + FAW_PM);

    const uint32_t Su = smem_u32(sm);
    const uint32_t Pu = Su + FAW_P * 4;

    const int t  = threadIdx.x;
    const int w  = t >> 5;
    const int ln = t & 31;
    const int g  = ln >> 2;
    const int q  = ln & 3;
    const int qt = (int)gridDim.x - 1 - (int)blockIdx.x;   // longest first
    const int h  = blockIdx.y;
    const int b  = blockIdx.z;
    const int q0 = qt * 64;
    const int wq = w * 16;

    // ldmatrix lane->address offsets (mapping verified: rel_err bit-stable)
    const int r8   = ln & 7;
    const int aRow = wq + ((ln >> 3) & 1) * 8 + r8;
    const int aCol = ((ln >> 4) & 1) * 8;
    const int kRow = ((ln >> 4) & 1) * 8 + r8;
    const int kCol = ((ln >> 3) & 1) * 8;
    const int vRow = ((ln >> 3) & 1) * 8 + r8;
    const int vCol = ((ln >> 4) & 1) * 8;

    const uint32_t aQbase = Su + (uint32_t)(aRow * 144 + aCol * 2);
    const uint32_t aPbase = Pu + (uint32_t)(aRow * 144 + aCol * 2);

    const __half* qb = qh + (size_t)((b * Hn + h) * Sn + q0) * HDn;
    const __half* kb = kh + (size_t)((b * Hn + h) * Sn) * HDn;
    const __half* vb = vh + (size_t)((b * Hn + h) * Sn) * HDn;

    // Prefetch K/V tile kt into buffer kt&1 via cp.async (one commit group)
    auto issue_kv = [&](int kt) {
        const int k0 = kt * 64;
        const uint32_t Kb = Su + (uint32_t)(FAW_K + (kt & 1) * FAW_K) * 4u;
        const uint32_t Vb = Su + (uint32_t)(FAW_V + (kt & 1) * FAW_K) * 4u;
#pragma unroll
        for (int i = 0; i < 4; i++) {
            const int cc  = t + 128 * i;
            const int row = cc >> 3;
            const int c8  = cc & 7;
            const uint32_t off = (uint32_t)(row * 144 + c8 * 16);
            CP16(Kb + off, &kb[(size_t)(k0 + row) * HDn + c8 * 8]);
            CP16(Vb + off, &vb[(size_t)(k0 + row) * HDn + c8 * 8]);
        }
        CP_COMMIT();
    };

    issue_kv(0);

    // Q tile: vectorized copy (already scaled + half) — overlaps with prefetch
#pragma unroll
    for (int i = 0; i < 4; i++) {
        const int cc  = t + 128 * i;
        const int row = cc >> 3;
        const int c8  = cc & 7;
        uint4 u = *(const uint4*)&qb[row * HDn + c8 * 8];
        *(uint4*)&Qs[row * PSTR + c8 * 4] = u;
    }

    float o[8][4];
#pragma unroll
    for (int dt = 0; dt < 8; dt++)
#pragma unroll
        for (int r = 0; r < 4; r++) o[dt][r] = 0.f;
    float mrow[2] = {-1e30f, -1e30f};
    float lrow[2] = {0.f, 0.f};

    const int r_lo = q0 + wq + g;
    const int r_hi = r_lo + 8;

    for (int kt = 0; kt <= qt; kt++) {
        const int k0 = kt * 64;
        const uint32_t Ku = Su + (uint32_t)(FAW_K + (kt & 1) * FAW_K) * 4u;
        const uint32_t Vu = Su + (uint32_t)(FAW_V + (kt & 1) * FAW_K) * 4u;

        if (kt + 1 <= qt) {            // prefetch next tile, then wait current
            issue_kv(kt + 1);
            CP_WAIT(1);
        } else {
            CP_WAIT(0);
        }
        // pad flags for this tile: 16 lanes x int4
        if (t < 16) {
            int4 pv = *(const int4*)&pad[b * Sn + k0 + t * 4];
            PM[t * 4 + 0] = (pv.x != 0) ? 1.f : 0.f;
            PM[t * 4 + 1] = (pv.y != 0) ? 1.f : 0.f;
            PM[t * 4 + 2] = (pv.z != 0) ? 1.f : 0.f;
            PM[t * 4 + 3] = (pv.w != 0) ? 1.f : 0.f;
        }
        __syncthreads();

        // ---- S = Q K^T ----
        float sv[8][4];
#pragma unroll
        for (int nt = 0; nt < 8; nt++)
#pragma unroll
            for (int r = 0; r < 4; r++) sv[nt][r] = 0.f;

#pragma unroll
        for (int kk = 0; kk < 4; kk++) {
            uint32_t a[4];
            LDSM4(a[0], a[1], a[2], a[3], aQbase + kk * 32);
#pragma unroll
            for (int p = 0; p < 4; p++) {
                uint32_t b0a, b1a, b0b, b1b;
                LDSM4(b0a, b1a, b0b, b1b,
                      Ku + (uint32_t)((16 * p + kRow) * 144 + (16 * kk + kCol) * 2));
                mma_f16(sv[2 * p],     a, b0a, b1a);
                mma_f16(sv[2 * p + 1], a, b0b, b1b);
            }
        }

        // ---- mask (replace semantics) ----
        const bool diag = (kt == qt);
#pragma unroll
        for (int nt = 0; nt < 8; nt++) {
            const int kx0 = nt * 8 + 2 * q;
            const bool pm0 = PM[kx0] != 0.f;
            const bool pm1 = PM[kx0 + 1] != 0.f;
            const int kg0 = k0 + kx0, kg1 = kg0 + 1;
            if (pm0 || (diag && kg0 > r_lo)) sv[nt][0] = NEGV;
            if (pm1 || (diag && kg1 > r_lo)) sv[nt][1] = NEGV;
            if (pm0 || (diag && kg0 > r_hi)) sv[nt][2] = NEGV;
            if (pm1 || (diag && kg1 > r_hi)) sv[nt][3] = NEGV;
        }

        // ---- online softmax ----
#pragma unroll
        for (int half = 0; half < 2; half++) {
            const int ci = half * 2;
            float tm = -1e30f;
#pragma unroll
            for (int nt = 0; nt < 8; nt++)
                tm = fmaxf(tm, fmaxf(sv[nt][ci], sv[nt][ci + 1]));
            tm = fmaxf(tm, __shfl_xor_sync(0xffffffffu, tm, 1));
            tm = fmaxf(tm, __shfl_xor_sync(0xffffffffu, tm, 2));
            const float mnew = fmaxf(mrow[half], tm);
            const float sc = __expf(mrow[half] - mnew);
            float rs = 0.f;
#pragma unroll
            for (int nt = 0; nt < 8; nt++) {
                const float p0 = __expf(sv[nt][ci]     - mnew);
                const float p1 = __expf(sv[nt][ci + 1] - mnew);
                sv[nt][ci] = p0; sv[nt][ci + 1] = p1;
                rs += p0 + p1;
            }
            rs += __shfl_xor_sync(0xffffffffu, rs, 1);
            rs += __shfl_xor_sync(0xffffffffu, rs, 2);
            lrow[half] = lrow[half] * sc + rs;
            mrow[half] = mnew;
#pragma unroll
            for (int dt = 0; dt < 8; dt++) {
                o[dt][ci]     *= sc;
                o[dt][ci + 1] *= sc;
            }
        }

        // ---- store P (natural row-major pairs) ----
#pragma unroll
        for (int nt = 0; nt < 8; nt++) {
            Ps[(wq + g)     * PSTR + 4 * nt + q] = pack_h2(sv[nt][0], sv[nt][1]);
            Ps[(wq + g + 8) * PSTR + 4 * nt + q] = pack_h2(sv[nt][2], sv[nt][3]);
        }
        __syncwarp();

        // ---- O += P V  (V transposed by ldmatrix.trans) ----
#pragma unroll
        for (int kk = 0; kk < 4; kk++) {
            uint32_t a[4];
            LDSM4(a[0], a[1], a[2], a[3], aPbase + kk * 32);
#pragma unroll
            for (int p = 0; p < 4; p++) {
                uint32_t b0a, b1a, b0b, b1b;
                LDSM4T(b0a, b1a, b0b, b1b,
                       Vu + (uint32_t)((16 * kk + vRow) * 144 + (16 * p + vCol) * 2));
                mma_f16(o[2 * p],     a, b0a, b1a);
                mma_f16(o[2 * p + 1], a, b0b, b1b);
            }
        }
        __syncthreads();   // all reads of buf kt&1 + PM done before refill
    }

    // ---- normalize + write half context ----
    const float inv_lo = 1.f / lrow[0];
    const float inv_hi = 1.f / lrow[1];
#pragma unroll
    for (int dt = 0; dt < 8; dt++) {
        const int col = h * HDn + dt * 8 + 2 * q;
        *(uint32_t*)&ctx[(size_t)(b * Sn + r_lo) * Dn + col] =
            pack_h2(o[dt][0] * inv_lo, o[dt][1] * inv_lo);
        *(uint32_t*)&ctx[(size_t)(b * Sn + r_hi) * Dn + col] =
            pack_h2(o[dt][2] * inv_hi, o[dt][3] * inv_hi);
    }
}

// ---------------------------------------------------------------------------
extern "C" void kernel_launch(void* const* d_in, const int* in_sizes, int n_in,
                              void* d_out, int out_size)
{
    const float* x    = (const float*)d_in[0];
    const int*   pm   = (const int*)d_in[1];
    const float* Wq   = (const float*)d_in[2];
    const float* bq   = (const float*)d_in[3];
    const float* Wk   = (const float*)d_in[4];
    const float* bk   = (const float*)d_in[5];
    const float* Wv   = (const float*)d_in[6];
    const float* bv   = (const float*)d_in[7];
    const float* Wo   = (const float*)d_in[8];
    const float* bo   = (const float*)d_in[9];
    float* out = (float*)d_out;

    __half *xh, *wh, *qh, *kh, *vh, *ctx;
    cudaGetSymbolAddress((void**)&xh,  g_xh);
    cudaGetSymbolAddress((void**)&wh,  g_wh);
    cudaGetSymbolAddress((void**)&qh,  g_qh);
    cudaGetSymbolAddress((void**)&kh,  g_kh);
    cudaGetSymbolAddress((void**)&vh,  g_vh);
    cudaGetSymbolAddress((void**)&ctx, g_ctx);

    cudaFuncSetAttribute(gemm_cp<1>, cudaFuncAttributeMaxDynamicSharedMemorySize,
                         GEMM_SMEM);
    cudaFuncSetAttribute(gemm_cp<0>, cudaFuncAttributeMaxDynamicSharedMemorySize,
                         GEMM_SMEM);
    cudaFuncSetAttribute(flash_attn_h, cudaFuncAttributeMaxDynamicSharedMemorySize,
                         FA_SMEM);

    cvt_inputs<<<8192, 256>>>((const float4*)x, (const float4*)Wq,
                              (const float4*)Wk, (const float4*)Wv,
                              (const float4*)Wo);

    const dim3 qkv_grid(24, (Bn * Sn) / BM);     // (24, 32)
    gemm_cp<1><<<qkv_grid, 256, GEMM_SMEM>>>(xh, wh, bq, bk, bv,
                                             qh, kh, vh, nullptr);

    dim3 agrid(Sn / 64, Hn, Bn);  // (32, 16, 2)
    flash_attn_h<<<agrid, 128, FA_SMEM>>>(qh, kh, vh, pm, ctx);

    const dim3 o_grid(Dn / BN, (Bn * Sn) / BM);  // (8, 32)
    gemm_cp<0><<<o_grid, 256, GEMM_SMEM>>>(ctx, wh + (size_t)3 * Dn * Dn,
                                           bo, nullptr, nullptr,
                                           nullptr, nullptr, nullptr, out);
}

// round 15
// speedup vs baseline: 1.5571x; 1.0362x over previous
#include <cuda_runtime.h>
#include <cuda_fp16.h>
#include <math.h>
#include <cstdint>

#define Bn 2
#define Sn 2048
#define Dn 1024
#define Hn 16
#define HDn 64
#define NEGV -1.0e9f

// Scratch (device globals: no allocations allowed)
__device__ __half g_xh[Bn*Sn*Dn];        // X in half
__device__ __half g_wh[4*Dn*Dn];         // Wq,Wk,Wv,Wo in half
__device__ __half g_qh[Bn*Hn*Sn*HDn];    // [B,H,S,HD] (pre-scaled by 0.125)
__device__ __half g_kh[Bn*Hn*Sn*HDn];
__device__ __half g_vh[Bn*Hn*Sn*HDn];
__device__ __half g_ctx[Bn*Sn*Dn];       // [B,S,D] context before Wo

__device__ __forceinline__ void mma_f16(float* c, const uint32_t* a,
                                        uint32_t b0, uint32_t b1) {
    asm volatile(
        "mma.sync.aligned.m16n8k16.row.col.f32.f16.f16.f32 "
        "{%0,%1,%2,%3}, {%4,%5,%6,%7}, {%8,%9}, {%0,%1,%2,%3};"
        : "+f"(c[0]), "+f"(c[1]), "+f"(c[2]), "+f"(c[3])
        : "r"(a[0]), "r"(a[1]), "r"(a[2]), "r"(a[3]), "r"(b0), "r"(b1));
}

__device__ __forceinline__ uint32_t pack_h2(float x, float y) {
    __half2 h = __floats2half2_rn(x, y);
    return *reinterpret_cast<uint32_t*>(&h);
}

__device__ __forceinline__ uint32_t smem_u32(const void* p) {
    uint32_t a;
    asm("{ .reg .u64 t; cvta.to.shared.u64 t, %1; cvt.u32.u64 %0, t; }"
        : "=r"(a) : "l"(p));
    return a;
}

#define CP16(dst_u32, src_ptr)                                               \
    asm volatile("cp.async.cg.shared.global [%0], [%1], 16;"                 \
                 :: "r"(dst_u32), "l"(src_ptr))
#define CP_COMMIT() asm volatile("cp.async.commit_group;" ::: "memory")
#define CP_WAIT(N)  asm volatile("cp.async.wait_group %0;" :: "n"(N) : "memory")

#define LDSM4(r0, r1, r2, r3, addr)                                          \
    asm volatile("ldmatrix.sync.aligned.m8n8.x4.shared.b16 {%0,%1,%2,%3}, [%4];" \
                 : "=r"(r0), "=r"(r1), "=r"(r2), "=r"(r3) : "r"(addr))
#define LDSM4T(r0, r1, r2, r3, addr)                                         \
    asm volatile("ldmatrix.sync.aligned.m8n8.x4.trans.shared.b16 {%0,%1,%2,%3}, [%4];" \
                 : "=r"(r0), "=r"(r1), "=r"(r2), "=r"(r3) : "r"(addr))

// ===========================================================================
// Pre-conversion: X + 4 weight matrices -> half.  (unchanged)
// ===========================================================================
__global__ void __launch_bounds__(256) cvt_inputs(const float4* __restrict__ X,
                                                  const float4* __restrict__ Wq,
                                                  const float4* __restrict__ Wk,
                                                  const float4* __restrict__ Wv,
                                                  const float4* __restrict__ Wo)
{
    const int idx = blockIdx.x * 256 + threadIdx.x;
    const int XQ = (Bn * Sn * Dn) / 4;
    float4 v;
    uint2* dst;
    if (idx < XQ) {
        v = X[idx];
        dst = reinterpret_cast<uint2*>(g_xh) + idx;
    } else {
        const int j = idx - XQ;
        const int which = j >> 18;
        const int off = j & ((1 << 18) - 1);
        const float4* W = (which == 0) ? Wq : (which == 1) ? Wk
                        : (which == 2) ? Wv : Wo;
        v = W[off];
        dst = reinterpret_cast<uint2*>(g_wh) + (which << 18) + off;
    }
    uint2 u;
    u.x = pack_h2(v.x, v.y);
    u.y = pack_h2(v.z, v.w);
    *dst = u;
}

// ===========================================================================
// fp16 cp.async GEMM, 3-stage pipeline + ldmatrix fragment loads.
// BM=128, BN=128, BK=64 halves (128B rows, chunk^(row&7) swizzle).
// 256 threads = 8 warps (4x2), warp tile 32x64.
// Fragment maps mirror the bit-exact-verified flash mappings:
//   A = Q-style (half_sel rows, quad_sel k-chunk), B = K-style (swapped).
// phys chunk = (2kk+sel)^r8: 8 distinct chunks per lane-octet => conflict-free.
// ===========================================================================
#define BM 128
#define BN 128
#define BKH2 64
#define GSTAGES (Dn / BKH2)
#define TILE_W 4096
#define GEMM_SMEM (6 * TILE_W * 4)       // 3 stages x (A+B) = 98304 B

template<int QKV>
__global__ void __launch_bounds__(256, 2)
gemm_cp(const __half* __restrict__ Xh,
        const __half* __restrict__ Wh,
        const float* __restrict__ bias0,
        const float* __restrict__ bias1,
        const float* __restrict__ bias2,
        __half* __restrict__ Y0,
        __half* __restrict__ Y1,
        __half* __restrict__ Y2,
        float* __restrict__ Yf)
{
    extern __shared__ uint32_t smem[];
    const uint32_t smem_b = smem_u32(smem);

    const int t  = threadIdx.x;
    const int w  = t >> 5;
    const int ln = t & 31;
    const int g  = ln >> 2;
    const int q  = ln & 3;
    const int r8 = ln & 7;
    const int half_sel = (ln >> 3) & 1;
    const int quad_sel = (ln >> 4) & 1;
    const int wm = (w & 3) * 32;
    const int wn = (w >> 2) * 64;
    const int rowBase = blockIdx.y * BM;

    int which = 0, colW = blockIdx.x * BN;
    if (QKV) { which = blockIdx.x >> 3; colW = (blockIdx.x & 7) * BN; }
    const __half* W    = Wh + (size_t)which * Dn * Dn;
    const float* bias  = (which == 0) ? bias0 : (which == 1) ? bias1 : bias2;
    __half*      Y     = (which == 0) ? Y0 : (which == 1) ? Y1 : Y2;
    const float  scale = (QKV && which == 0) ? 0.125f : 1.0f;

    float acc[2][8][4];
#pragma unroll
    for (int mt = 0; mt < 2; mt++)
#pragma unroll
        for (int nt = 0; nt < 8; nt++)
#pragma unroll
            for (int r = 0; r < 4; r++) acc[mt][nt][r] = 0.f;

    auto issue = [&](int s) {
        const int buf = s % 3;
        const int k0 = s * BKH2;
        const uint32_t aB = smem_b + (buf * 2 * TILE_W) * 4;
        const uint32_t bB = aB + TILE_W * 4;
#pragma unroll
        for (int i = 0; i < 4; i++) {
            const int e = t + 256 * i;
            const int m = e >> 3, c = e & 7;
            const uint32_t swoff = (uint32_t)(m * 128 + ((c ^ (m & 7)) << 4));
            CP16(aB + swoff, &Xh[(size_t)(rowBase + m) * Dn + k0 + c * 8]);
            CP16(bB + swoff, &W[(size_t)(colW + m) * Dn + k0 + c * 8]);
        }
        CP_COMMIT();
    };

    auto comp = [&](int buf) {
        const uint32_t aB = smem_b + (buf * 2 * TILE_W) * 4;
        const uint32_t bB = aB + TILE_W * 4;
        // per-lane row bases (A: half_sel rows; B: quad_sel rows)
        const uint32_t aAddr0 = aB + (uint32_t)((wm + half_sel * 8 + r8) * 128);
        const uint32_t aAddr1 = aAddr0 + 16 * 128;
        uint32_t bAddr[4];
#pragma unroll
        for (int np = 0; np < 4; np++)
            bAddr[np] = bB + (uint32_t)((wn + np * 16 + quad_sel * 8 + r8) * 128);

#pragma unroll
        for (int kk = 0; kk < 4; kk++) {
            const uint32_t oA = (uint32_t)(((2 * kk + quad_sel) ^ r8) << 4);
            const uint32_t oB = (uint32_t)(((2 * kk + half_sel) ^ r8) << 4);
            uint32_t a0[4], a1[4];
            LDSM4(a0[0], a0[1], a0[2], a0[3], aAddr0 + oA);
            LDSM4(a1[0], a1[1], a1[2], a1[3], aAddr1 + oA);
#pragma unroll
            for (int np = 0; np < 4; np++) {
                uint32_t b0a, b1a, b0b, b1b;
                LDSM4(b0a, b1a, b0b, b1b, bAddr[np] + oB);
                mma_f16(acc[0][2 * np],     a0, b0a, b1a);
                mma_f16(acc[0][2 * np + 1], a0, b0b, b1b);
                mma_f16(acc[1][2 * np],     a1, b0a, b1a);
                mma_f16(acc[1][2 * np + 1], a1, b0b, b1b);
            }
        }
    };

    issue(0);
    issue(1);
    issue(2);
    for (int s = 0; s < GSTAGES; s++) {
        if (s + 2 < GSTAGES)      CP_WAIT(2);
        else if (s + 1 < GSTAGES) CP_WAIT(1);
        else                      CP_WAIT(0);
        __syncthreads();
        comp(s % 3);
        if (s + 3 < GSTAGES) {
            __syncthreads();            // all reads of buf s%3 done
            issue(s + 3);
        }
    }

#pragma unroll
    for (int nt = 0; nt < 8; nt++) {
        const int c = colW + wn + nt * 8 + 2 * q;
        const float b0 = bias[c], b1 = bias[c + 1];
#pragma unroll
        for (int mt = 0; mt < 2; mt++) {
            const int r0 = rowBase + wm + mt * 16 + g;
#pragma unroll
            for (int half = 0; half < 2; half++) {
                const int rr = r0 + half * 8;
                const float vx = (acc[mt][nt][half * 2 + 0] + b0) * scale;
                const float vy = (acc[mt][nt][half * 2 + 1] + b1) * scale;
                if (QKV) {
                    const int bb = rr >> 11;
                    const int ss = rr & (Sn - 1);
                    const int hh = c >> 6;
                    const int dd = c & (HDn - 1);
                    *(uint32_t*)&Y[(size_t)((bb * Hn + hh) * Sn + ss) * HDn + dd] =
                        pack_h2(vx, vy);
                } else {
                    float2 v; v.x = vx; v.y = vy;
                    *(float2*)&Yf[(size_t)rr * Dn + c] = v;
                }
            }
        }
    }
}

// ===========================================================================
// Flash attention (unchanged from R14 — cp.async K/V + ldmatrix, ~85us)
// ===========================================================================
#define PSTR 36
#define FAW_K 2304
#define FAW_V 6912
#define FAW_P 11520
#define FAW_PM 13824
#define FA_SMEM ((13824 + 64) * 4)           // 55552 B

__global__ void __launch_bounds__(128) flash_attn_h(const __half* __restrict__ qh,
                                                    const __half* __restrict__ kh,
                                                    const __half* __restrict__ vh,
                                                    const int* __restrict__ pad,
                                                    __half* __restrict__ ctx)
{
    extern __shared__ uint32_t sm[];
    uint32_t* Qs = sm;
    uint32_t* Ps = sm + FAW_P;
    float*    PM = (float*)(sm + FAW_PM);

    const uint32_t Su = smem_u32(sm);
    const uint32_t Pu = Su + FAW_P * 4;

    const int t  = threadIdx.x;
    const int w  = t >> 5;
    const int ln = t & 31;
    const int g  = ln >> 2;
    const int q  = ln & 3;
    const int qt = (int)gridDim.x - 1 - (int)blockIdx.x;   // longest first
    const int h  = blockIdx.y;
    const int b  = blockIdx.z;
    const int q0 = qt * 64;
    const int wq = w * 16;

    const int r8   = ln & 7;
    const int aRow = wq + ((ln >> 3) & 1) * 8 + r8;
    const int aCol = ((ln >> 4) & 1) * 8;
    const int kRow = ((ln >> 4) & 1) * 8 + r8;
    const int kCol = ((ln >> 3) & 1) * 8;
    const int vRow = ((ln >> 3) & 1) * 8 + r8;
    const int vCol = ((ln >> 4) & 1) * 8;

    const uint32_t aQbase = Su + (uint32_t)(aRow * 144 + aCol * 2);
    const uint32_t aPbase = Pu + (uint32_t)(aRow * 144 + aCol * 2);

    const __half* qb = qh + (size_t)((b * Hn + h) * Sn + q0) * HDn;
    const __half* kb = kh + (size_t)((b * Hn + h) * Sn) * HDn;
    const __half* vb = vh + (size_t)((b * Hn + h) * Sn) * HDn;

    auto issue_kv = [&](int kt) {
        const int k0 = kt * 64;
        const uint32_t Kb = Su + (uint32_t)(FAW_K + (kt & 1) * FAW_K) * 4u;
        const uint32_t Vb = Su + (uint32_t)(FAW_V + (kt & 1) * FAW_K) * 4u;
#pragma unroll
        for (int i = 0; i < 4; i++) {
            const int cc  = t + 128 * i;
            const int row = cc >> 3;
            const int c8  = cc & 7;
            const uint32_t off = (uint32_t)(row * 144 + c8 * 16);
            CP16(Kb + off, &kb[(size_t)(k0 + row) * HDn + c8 * 8]);
            CP16(Vb + off, &vb[(size_t)(k0 + row) * HDn + c8 * 8]);
        }
        CP_COMMIT();
    };

    issue_kv(0);

#pragma unroll
    for (int i = 0; i < 4; i++) {
        const int cc  = t + 128 * i;
        const int row = cc >> 3;
        const int c8  = cc & 7;
        uint4 u = *(const uint4*)&qb[row * HDn + c8 * 8];
        *(uint4*)&Qs[row * PSTR + c8 * 4] = u;
    }

    float o[8][4];
#pragma unroll
    for (int dt = 0; dt < 8; dt++)
#pragma unroll
        for (int r = 0; r < 4; r++) o[dt][r] = 0.f;
    float mrow[2] = {-1e30f, -1e30f};
    float lrow[2] = {0.f, 0.f};

    const int r_lo = q0 + wq + g;
    const int r_hi = r_lo + 8;

    for (int kt = 0; kt <= qt; kt++) {
        const int k0 = kt * 64;
        const uint32_t Ku = Su + (uint32_t)(FAW_K + (kt & 1) * FAW_K) * 4u;
        const uint32_t Vu = Su + (uint32_t)(FAW_V + (kt & 1) * FAW_K) * 4u;

        if (kt + 1 <= qt) {
            issue_kv(kt + 1);
            CP_WAIT(1);
        } else {
            CP_WAIT(0);
        }
        if (t < 16) {
            int4 pv = *(const int4*)&pad[b * Sn + k0 + t * 4];
            PM[t * 4 + 0] = (pv.x != 0) ? 1.f : 0.f;
            PM[t * 4 + 1] = (pv.y != 0) ? 1.f : 0.f;
            PM[t * 4 + 2] = (pv.z != 0) ? 1.f : 0.f;
            PM[t * 4 + 3] = (pv.w != 0) ? 1.f : 0.f;
        }
        __syncthreads();

        // ---- S = Q K^T ----
        float sv[8][4];
#pragma unroll
        for (int nt = 0; nt < 8; nt++)
#pragma unroll
            for (int r = 0; r < 4; r++) sv[nt][r] = 0.f;

#pragma unroll
        for (int kk = 0; kk < 4; kk++) {
            uint32_t a[4];
            LDSM4(a[0], a[1], a[2], a[3], aQbase + kk * 32);
#pragma unroll
            for (int p = 0; p < 4; p++) {
                uint32_t b0a, b1a, b0b, b1b;
                LDSM4(b0a, b1a, b0b, b1b,
                      Ku + (uint32_t)((16 * p + kRow) * 144 + (16 * kk + kCol) * 2));
                mma_f16(sv[2 * p],     a, b0a, b1a);
                mma_f16(sv[2 * p + 1], a, b0b, b1b);
            }
        }

        // ---- mask ----
        const bool diag = (kt == qt);
#pragma unroll
        for (int nt = 0; nt < 8; nt++) {
            const int kx0 = nt * 8 + 2 * q;
            const bool pm0 = PM[kx0] != 0.f;
            const bool pm1 = PM[kx0 + 1] != 0.f;
            const int kg0 = k0 + kx0, kg1 = kg0 + 1;
            if (pm0 || (diag && kg0 > r_lo)) sv[nt][0] = NEGV;
            if (pm1 || (diag && kg1 > r_lo)) sv[nt][1] = NEGV;
            if (pm0 || (diag && kg0 > r_hi)) sv[nt][2] = NEGV;
            if (pm1 || (diag && kg1 > r_hi)) sv[nt][3] = NEGV;
        }

        // ---- online softmax ----
#pragma unroll
        for (int half = 0; half < 2; half++) {
            const int ci = half * 2;
            float tm = -1e30f;
#pragma unroll
            for (int nt = 0; nt < 8; nt++)
                tm = fmaxf(tm, fmaxf(sv[nt][ci], sv[nt][ci + 1]));
            tm = fmaxf(tm, __shfl_xor_sync(0xffffffffu, tm, 1));
            tm = fmaxf(tm, __shfl_xor_sync(0xffffffffu, tm, 2));
            const float mnew = fmaxf(mrow[half], tm);
            const float sc = __expf(mrow[half] - mnew);
            float rs = 0.f;
#pragma unroll
            for (int nt = 0; nt < 8; nt++) {
                const float p0 = __expf(sv[nt][ci]     - mnew);
                const float p1 = __expf(sv[nt][ci + 1] - mnew);
                sv[nt][ci] = p0; sv[nt][ci + 1] = p1;
                rs += p0 + p1;
            }
            rs += __shfl_xor_sync(0xffffffffu, rs, 1);
            rs += __shfl_xor_sync(0xffffffffu, rs, 2);
            lrow[half] = lrow[half] * sc + rs;
            mrow[half] = mnew;
#pragma unroll
            for (int dt = 0; dt < 8; dt++) {
                o[dt][ci]     *= sc;
                o[dt][ci + 1] *= sc;
            }
        }

        // ---- store P ----
#pragma unroll
        for (int nt = 0; nt < 8; nt++) {
            Ps[(wq + g)     * PSTR + 4 * nt + q] = pack_h2(sv[nt][0], sv[nt][1]);
            Ps[(wq + g + 8) * PSTR + 4 * nt + q] = pack_h2(sv[nt][2], sv[nt][3]);
        }
        __syncwarp();

        // ---- O += P V ----
#pragma unroll
        for (int kk = 0; kk < 4; kk++) {
            uint32_t a[4];
            LDSM4(a[0], a[1], a[2], a[3], aPbase + kk * 32);
#pragma unroll
            for (int p = 0; p < 4; p++) {
                uint32_t b0a, b1a, b0b, b1b;
                LDSM4T(b0a, b1a, b0b, b1b,
                       Vu + (uint32_t)((16 * kk + vRow) * 144 + (16 * p + vCol) * 2));
                mma_f16(o[2 * p],     a, b0a, b1a);
                mma_f16(o[2 * p + 1], a, b0b, b1b);
            }
        }
        __syncthreads();
    }

    const float inv_lo = 1.f / lrow[0];
    const float inv_hi = 1.f / lrow[1];
#pragma unroll
    for (int dt = 0; dt < 8; dt++) {
        const int col = h * HDn + dt * 8 + 2 * q;
        *(uint32_t*)&ctx[(size_t)(b * Sn + r_lo) * Dn + col] =
            pack_h2(o[dt][0] * inv_lo, o[dt][1] * inv_lo);
        *(uint32_t*)&ctx[(size_t)(b * Sn + r_hi) * Dn + col] =
            pack_h2(o[dt][2] * inv_hi, o[dt][3] * inv_hi);
    }
}

// ---------------------------------------------------------------------------
extern "C" void kernel_launch(void* const* d_in, const int* in_sizes, int n_in,
                              void* d_out, int out_size)
{
    const float* x    = (const float*)d_in[0];
    const int*   pm   = (const int*)d_in[1];
    const float* Wq   = (const float*)d_in[2];
    const float* bq   = (const float*)d_in[3];
    const float* Wk   = (const float*)d_in[4];
    const float* bk   = (const float*)d_in[5];
    const float* Wv   = (const float*)d_in[6];
    const float* bv   = (const float*)d_in[7];
    const float* Wo   = (const float*)d_in[8];
    const float* bo   = (const float*)d_in[9];
    float* out = (float*)d_out;

    __half *xh, *wh, *qh, *kh, *vh, *ctx;
    cudaGetSymbolAddress((void**)&xh,  g_xh);
    cudaGetSymbolAddress((void**)&wh,  g_wh);
    cudaGetSymbolAddress((void**)&qh,  g_qh);
    cudaGetSymbolAddress((void**)&kh,  g_kh);
    cudaGetSymbolAddress((void**)&vh,  g_vh);
    cudaGetSymbolAddress((void**)&ctx, g_ctx);

    cudaFuncSetAttribute(gemm_cp<1>, cudaFuncAttributeMaxDynamicSharedMemorySize,
                         GEMM_SMEM);
    cudaFuncSetAttribute(gemm_cp<0>, cudaFuncAttributeMaxDynamicSharedMemorySize,
                         GEMM_SMEM);
    cudaFuncSetAttribute(flash_attn_h, cudaFuncAttributeMaxDynamicSharedMemorySize,
                         FA_SMEM);

    cvt_inputs<<<8192, 256>>>((const float4*)x, (const float4*)Wq,
                              (const float4*)Wk, (const float4*)Wv,
                              (const float4*)Wo);

    const dim3 qkv_grid(24, (Bn * Sn) / BM);     // (24, 32)
    gemm_cp<1><<<qkv_grid, 256, GEMM_SMEM>>>(xh, wh, bq, bk, bv,
                                             qh, kh, vh, nullptr);

    dim3 agrid(Sn / 64, Hn, Bn);  // (32, 16, 2)
    flash_attn_h<<<agrid, 128, FA_SMEM>>>(qh, kh, vh, pm, ctx);

    const dim3 o_grid(Dn / BN, (Bn * Sn) / BM);  // (8, 32)
    gemm_cp<0><<<o_grid, 256, GEMM_SMEM>>>(ctx, wh + (size_t)3 * Dn * Dn,
                                           bo, nullptr, nullptr,
                                           nullptr, nullptr, nullptr, out);
}